// round 5
// baseline (speedup 1.0000x reference)
#include <cuda_runtime.h>

#define NB 32
#define NK 128
#define NV 5000
#define NC 256
#define LMBDA 100.0f

typedef unsigned long long u64;

// ---------------- scratch (device globals; allocation is forbidden) --------
__device__ __align__(256) float g_Ax[NB*NK*NC];     // 4 MB
__device__ __align__(256) float g_Ay[NB*NK*NC];     // 4 MB
__device__ __align__(256) float g_AAxx[NB*NK*NK];   // 2 MB
__device__ __align__(256) float g_AAyx[NB*NK*NK];   // 2 MB
__device__ __align__(256) float g_W[NB*NK*NK];      // 2 MB : AA_xx^{-1}
__device__ __align__(256) float g_Mt[NB*NK*NK];     // 2 MB : LMBDA * MASK
__device__ __align__(256) float g_E[NB*NK*NK];      // 2 MB : residual

// ---------------- packed f32x2 helpers -------------------------------------
static __device__ __forceinline__ u64 pk2(float lo, float hi){
    u64 d; asm("mov.b64 %0, {%1,%2};" : "=l"(d) : "f"(lo), "f"(hi)); return d;
}
static __device__ __forceinline__ void up2(u64 v, float &lo, float &hi){
    asm("mov.b64 {%0,%1}, %2;" : "=f"(lo), "=f"(hi) : "l"(v));
}
static __device__ __forceinline__ u64 f2fma(u64 a, u64 b, u64 c){
    u64 d; asm("fma.rn.f32x2 %0, %1, %2, %3;" : "=l"(d) : "l"(a), "l"(b), "l"(c)); return d;
}
static __device__ __forceinline__ u64 f2mul(u64 a, u64 b){
    u64 d; asm("mul.rn.f32x2 %0, %1, %2;" : "=l"(d) : "l"(a), "l"(b)); return d;
}

// ============================================================================
// Kernel 1: A = pinv @ feat   per (b, which): 128x5000 @ 5000x(64-col tile)
// grid (4 n-tiles, 32 batches, 2 which), 256 threads.
// BM=128, BN=64, BK=8 double-buffered. Row-pair accumulators: each u64 acc
// holds (C[2p][j], C[2p+1][j]); A read as LDS.64 pairs, only B duplicated.
// ============================================================================
__global__ __launch_bounds__(256,2)
void k_gemmA(const float* __restrict__ Px, const float* __restrict__ Fx,
             const float* __restrict__ Py, const float* __restrict__ Fy)
{
    const int b = blockIdx.y, nt = blockIdx.x;
    const bool wy = (blockIdx.z != 0);
    const float* __restrict__ P = (wy ? Py : Px) + (size_t)b*NK*NV;
    const float* __restrict__ F = (wy ? Fy : Fx) + (size_t)b*NV*NC + nt*64;
    float* __restrict__ O = (wy ? g_Ay : g_Ax) + (size_t)b*NK*NC + nt*64;

    __shared__ __align__(16) float As[2][8][132];   // k-major: As[k][m]
    __shared__ __align__(16) float Bs[2][8][68];    // Bs[k][n]

    const int t  = threadIdx.x;
    const int tx = t & 15, ty = t >> 4;
    const int am = t >> 1, aq = t & 1;        // A loader (all 256 threads)
    const int br = t >> 4, bc = t & 15;       // B loader (t < 128)
    const bool bload = (t < 128);

    u64 acc[4][4];
#pragma unroll
    for (int p=0;p<4;p++){ acc[p][0]=0ULL; acc[p][1]=0ULL; acc[p][2]=0ULL; acc[p][3]=0ULL; }

    {   // prologue: tile 0
        float4 av = *(const float4*)(P + (size_t)am*NV + aq*4);
        As[0][aq*4+0][am]=av.x; As[0][aq*4+1][am]=av.y;
        As[0][aq*4+2][am]=av.z; As[0][aq*4+3][am]=av.w;
        if (bload){
            float4 bv = *(const float4*)(F + (size_t)br*NC + bc*4);
            *(float4*)&Bs[0][br][bc*4] = bv;
        }
    }
    __syncthreads();

    int cur = 0;
    const int NS = NV/8;   // 625, exact
#pragma unroll 1
    for (int kk=0; kk<NS; kk++){
        float4 av, bv;
        const bool more = (kk+1 < NS);
        if (more){
            av = *(const float4*)(P + (size_t)am*NV + (kk+1)*8 + aq*4);
            if (bload)
                bv = *(const float4*)(F + (size_t)((kk+1)*8+br)*NC + bc*4);
        }
#pragma unroll
        for (int k=0;k<8;k++){
            const u64* ap = (const u64*)&As[cur][k][ty*8];
            u64 a0=ap[0], a1=ap[1], a2=ap[2], a3=ap[3];
            float4 b4 = *(const float4*)&Bs[cur][k][tx*4];
            u64 b0=pk2(b4.x,b4.x), b1=pk2(b4.y,b4.y);
            u64 b2=pk2(b4.z,b4.z), b3=pk2(b4.w,b4.w);
            acc[0][0]=f2fma(a0,b0,acc[0][0]); acc[0][1]=f2fma(a0,b1,acc[0][1]);
            acc[0][2]=f2fma(a0,b2,acc[0][2]); acc[0][3]=f2fma(a0,b3,acc[0][3]);
            acc[1][0]=f2fma(a1,b0,acc[1][0]); acc[1][1]=f2fma(a1,b1,acc[1][1]);
            acc[1][2]=f2fma(a1,b2,acc[1][2]); acc[1][3]=f2fma(a1,b3,acc[1][3]);
            acc[2][0]=f2fma(a2,b0,acc[2][0]); acc[2][1]=f2fma(a2,b1,acc[2][1]);
            acc[2][2]=f2fma(a2,b2,acc[2][2]); acc[2][3]=f2fma(a2,b3,acc[2][3]);
            acc[3][0]=f2fma(a3,b0,acc[3][0]); acc[3][1]=f2fma(a3,b1,acc[3][1]);
            acc[3][2]=f2fma(a3,b2,acc[3][2]); acc[3][3]=f2fma(a3,b3,acc[3][3]);
        }
        if (more){
            As[cur^1][aq*4+0][am]=av.x; As[cur^1][aq*4+1][am]=av.y;
            As[cur^1][aq*4+2][am]=av.z; As[cur^1][aq*4+3][am]=av.w;
            if (bload) *(float4*)&Bs[cur^1][br][bc*4] = bv;
            __syncthreads();
            cur ^= 1;
        }
    }
#pragma unroll
    for (int p=0;p<4;p++){
        float4 r0, r1;
        up2(acc[p][0], r0.x, r1.x);
        up2(acc[p][1], r0.y, r1.y);
        up2(acc[p][2], r0.z, r1.z);
        up2(acc[p][3], r0.w, r1.w);
        *(float4*)(O + (size_t)(ty*8+2*p  )*NC + tx*4) = r0;
        *(float4*)(O + (size_t)(ty*8+2*p+1)*NC + tx*4) = r1;
    }
}

// ============================================================================
// Kernel 2: AA_xx = A_x A_x^T ; AA_yx = A_y A_x^T  (per b: 128x128, K=256)
// grid (2 which, 32 batches), 256 threads, 8x8 tile (4 row-pairs x 8 cols).
// ============================================================================
__global__ __launch_bounds__(256,1)
void k_AA()
{
    const int b = blockIdx.y;
    const bool yx = (blockIdx.x != 0);
    const float* __restrict__ U = (yx ? g_Ay : g_Ax) + (size_t)b*NK*NC;
    const float* __restrict__ V = g_Ax + (size_t)b*NK*NC;
    float* __restrict__ O = (yx ? g_AAyx : g_AAxx) + (size_t)b*NK*NK;

    __shared__ __align__(16) float Us[2][8][132];
    __shared__ __align__(16) float Vs[2][8][132];

    const int t = threadIdx.x, tx = t&15, ty = t>>4;
    const int um = t>>1, uq = t&1;

    u64 acc[4][8];
#pragma unroll
    for (int p=0;p<4;p++)
#pragma unroll
        for (int j=0;j<8;j++) acc[p][j]=0ULL;

    {
        float4 uv = *(const float4*)(U + (size_t)um*NC + uq*4);
        float4 vv = *(const float4*)(V + (size_t)um*NC + uq*4);
        Us[0][uq*4+0][um]=uv.x; Us[0][uq*4+1][um]=uv.y; Us[0][uq*4+2][um]=uv.z; Us[0][uq*4+3][um]=uv.w;
        Vs[0][uq*4+0][um]=vv.x; Vs[0][uq*4+1][um]=vv.y; Vs[0][uq*4+2][um]=vv.z; Vs[0][uq*4+3][um]=vv.w;
    }
    __syncthreads();

    int cur = 0;
#pragma unroll 1
    for (int kk=0; kk<NC/8; kk++){
        float4 uv, vv;
        const bool more = (kk+1 < NC/8);
        if (more){
            uv = *(const float4*)(U + (size_t)um*NC + (kk+1)*8 + uq*4);
            vv = *(const float4*)(V + (size_t)um*NC + (kk+1)*8 + uq*4);
        }
#pragma unroll
        for (int k=0;k<8;k++){
            const u64* ap = (const u64*)&Us[cur][k][ty*8];
            u64 a0=ap[0], a1=ap[1], a2=ap[2], a3=ap[3];
            float4 c0 = *(const float4*)&Vs[cur][k][tx*8];
            float4 c1 = *(const float4*)&Vs[cur][k][tx*8+4];
            u64 bb[8];
            bb[0]=pk2(c0.x,c0.x); bb[1]=pk2(c0.y,c0.y);
            bb[2]=pk2(c0.z,c0.z); bb[3]=pk2(c0.w,c0.w);
            bb[4]=pk2(c1.x,c1.x); bb[5]=pk2(c1.y,c1.y);
            bb[6]=pk2(c1.z,c1.z); bb[7]=pk2(c1.w,c1.w);
#pragma unroll
            for (int j=0;j<8;j++){
                acc[0][j]=f2fma(a0,bb[j],acc[0][j]);
                acc[1][j]=f2fma(a1,bb[j],acc[1][j]);
                acc[2][j]=f2fma(a2,bb[j],acc[2][j]);
                acc[3][j]=f2fma(a3,bb[j],acc[3][j]);
            }
        }
        if (more){
            Us[cur^1][uq*4+0][um]=uv.x; Us[cur^1][uq*4+1][um]=uv.y; Us[cur^1][uq*4+2][um]=uv.z; Us[cur^1][uq*4+3][um]=uv.w;
            Vs[cur^1][uq*4+0][um]=vv.x; Vs[cur^1][uq*4+1][um]=vv.y; Vs[cur^1][uq*4+2][um]=vv.z; Vs[cur^1][uq*4+3][um]=vv.w;
            __syncthreads();
            cur ^= 1;
        }
    }
#pragma unroll
    for (int p=0;p<4;p++){
        float4 r0a, r0b, r1a, r1b;
        up2(acc[p][0], r0a.x, r1a.x); up2(acc[p][1], r0a.y, r1a.y);
        up2(acc[p][2], r0a.z, r1a.z); up2(acc[p][3], r0a.w, r1a.w);
        up2(acc[p][4], r0b.x, r1b.x); up2(acc[p][5], r0b.y, r1b.y);
        up2(acc[p][6], r0b.z, r1b.z); up2(acc[p][7], r0b.w, r1b.w);
        *(float4*)(O + (size_t)(ty*8+2*p  )*NK + tx*8)     = r0a;
        *(float4*)(O + (size_t)(ty*8+2*p  )*NK + tx*8 + 4) = r0b;
        *(float4*)(O + (size_t)(ty*8+2*p+1)*NK + tx*8)     = r1a;
        *(float4*)(O + (size_t)(ty*8+2*p+1)*NK + tx*8 + 4) = r1b;
    }
}

// ============================================================================
// Kernel 3: Mt[b,i,k] = LMBDA * MASK[b,i,k]
//   rows i <- evals_y terms, cols k <- evals_x terms (matches reference).
// ============================================================================
__global__ void k_mask(const float* __restrict__ evx, const float* __restrict__ evy)
{
    __shared__ float f1[NK], h1[NK], f2[NK], h2[NK], red[NK];
    const int b = blockIdx.x, t = threadIdx.x;
    float ex = evx[b*NK+t], ey = evy[b*NK+t];
    red[t] = fmaxf(ex, ey);
    __syncthreads();
    for (int s=64; s>0; s>>=1){
        if (t<s) red[t] = fmaxf(red[t], red[t+s]);
        __syncthreads();
    }
    const float scale = red[0];
    float e1 = sqrtf(ex/scale);
    float e2 = sqrtf(ey/scale);
    float d1 = 1.0f/(e1*e1+1.0f);
    float d2 = 1.0f/(e2*e2+1.0f);
    f1[t] = e1*d1; h1[t] = d1;
    f2[t] = e2*d2; h2[t] = d2;
    __syncthreads();
    const float mf1 = f1[t], mh1 = h1[t];
    float* out = g_Mt + (size_t)b*NK*NK;
#pragma unroll 4
    for (int i=0;i<NK;i++){
        float dre = f2[i]-mf1, dim = h2[i]-mh1;
        out[(size_t)i*NK + t] = LMBDA*(dre*dre + dim*dim);
    }
}

// ============================================================================
// Kernel 4: register-resident Gauss-Jordan inverse: g_W[b] = inv(AA_xx[b])
// One block per b, 256 threads. Thread (rb,cb) owns an 8x8 block as u64[8][4]
// (packed f32x2 column pairs). Per pivot j: publish factor column + scaled
// pivot row via double-buffered shared; 2 barriers per step. SPD, no pivot.
// ============================================================================
__global__ __launch_bounds__(256,1)
void k_gj()
{
    const int b = blockIdx.x, t = threadIdx.x;
    const int rb = t >> 4, cb = t & 15;     // 16x16 grid of 8x8 blocks
    const float* __restrict__ A = g_AAxx + (size_t)b*NK*NK;
    float* __restrict__ W = g_W + (size_t)b*NK*NK;

    __shared__ __align__(16) float prow[2][NK];
    __shared__ __align__(16) float fcol[2][NK];

    u64 M[8][4];
#pragma unroll
    for (int r=0;r<8;r++){
        const u64* src = (const u64*)(A + (size_t)(rb*8+r)*NK + cb*8);
        M[r][0]=src[0]; M[r][1]=src[1]; M[r][2]=src[2]; M[r][3]=src[3];
    }

#pragma unroll 1
    for (int j=0;j<NK;j++){
        const int jb = j>>3, jr = j&7, pb = j&1;
        if (cb == jb){
#pragma unroll
            for (int r=0;r<8;r++){
                float lo,hi; up2(M[r][jr>>1], lo, hi);
                fcol[pb][rb*8+r] = (jr&1) ? hi : lo;
            }
        }
        __syncthreads();
        const float d  = fcol[pb][j];
        const float inv = __frcp_rn(d);
        if (rb == jb){
            const u64 iv2 = pk2(inv,inv);
#pragma unroll
            for (int c=0;c<4;c++) M[jr][c] = f2mul(M[jr][c], iv2);
            if (cb == jb){
                float lo,hi; up2(M[jr][jr>>1], lo, hi);
                if (jr&1) hi = inv; else lo = inv;
                M[jr][jr>>1] = pk2(lo,hi);
            }
#pragma unroll
            for (int c=0;c<4;c++)
                *(u64*)&prow[pb][cb*8 + c*2] = M[jr][c];
        }
        __syncthreads();
        u64 p2[4];
#pragma unroll
        for (int c=0;c<4;c++) p2[c] = *(const u64*)&prow[pb][cb*8 + c*2];
#pragma unroll
        for (int r=0;r<8;r++){
            const float fr = fcol[pb][rb*8+r];
            const bool piv = (rb==jb) && (r==jr);
            const float frz = piv ? 0.0f : fr;
            const u64 nf2 = pk2(-frz, -frz);
            M[r][0] = f2fma(nf2, p2[0], M[r][0]);
            M[r][1] = f2fma(nf2, p2[1], M[r][1]);
            M[r][2] = f2fma(nf2, p2[2], M[r][2]);
            M[r][3] = f2fma(nf2, p2[3], M[r][3]);
            if (cb == jb && !piv){
                float lo,hi; up2(M[r][jr>>1], lo, hi);
                float v = -fr*inv;
                if (jr&1) hi = v; else lo = v;
                M[r][jr>>1] = pk2(lo,hi);
            }
        }
    }
#pragma unroll
    for (int r=0;r<8;r++){
        u64* dst = (u64*)(W + (size_t)(rb*8+r)*NK + cb*8);
        dst[0]=M[r][0]; dst[1]=M[r][1]; dst[2]=M[r][2]; dst[3]=M[r][3];
    }
}

// ============================================================================
// Kernel 5: solve steps (per b, 64-row halves; 4 rows x 8 cols per thread)
//   mode 0: X = R * W            (R = AA_yx)
//   mode 1: E = R - X*AA_xx - Mt .* X
//   mode 2: X += E * W
// ============================================================================
__global__ __launch_bounds__(256,2)
void k_step(float* __restrict__ X, int mode)
{
    const int b = blockIdx.y, half = blockIdx.x;
    const size_t boff = (size_t)b*NK*NK;
    const size_t hoff = boff + (size_t)half*64*NK;

    const float* A; const float* Bm; float* C;
    if (mode==0)      { A = g_AAyx + hoff; Bm = g_W    + boff; C = X   + hoff; }
    else if (mode==1) { A = X      + hoff; Bm = g_AAxx + boff; C = g_E + hoff; }
    else              { A = g_E    + hoff; Bm = g_W    + boff; C = X   + hoff; }

    __shared__ __align__(16) float As[2][16][68];    // As[k][m], m<64
    __shared__ __align__(16) float Bs[2][16][132];   // Bs[k][n]

    const int t = threadIdx.x;
    const int tx = t&15, ty = t>>4;
    const int am = t>>2, aq = t&3;
    const int br = t>>5, bc = t&31;

    u64 acc[2][8];
#pragma unroll
    for (int p=0;p<2;p++)
#pragma unroll
        for (int j=0;j<8;j++) acc[p][j]=0ULL;

    {
        float4 av = *(const float4*)(A + (size_t)am*NK + aq*4);
        As[0][aq*4+0][am]=av.x; As[0][aq*4+1][am]=av.y;
        As[0][aq*4+2][am]=av.z; As[0][aq*4+3][am]=av.w;
        float4 b0 = *(const float4*)(Bm + (size_t)br*NK + bc*4);
        float4 b1 = *(const float4*)(Bm + (size_t)(br+8)*NK + bc*4);
        *(float4*)&Bs[0][br][bc*4]   = b0;
        *(float4*)&Bs[0][br+8][bc*4] = b1;
    }
    __syncthreads();

    int cur = 0;
#pragma unroll 1
    for (int kk=0; kk<8; kk++){
        float4 av, q0, q1;
        const bool more = (kk < 7);
        if (more){
            av = *(const float4*)(A + (size_t)am*NK + (kk+1)*16 + aq*4);
            q0 = *(const float4*)(Bm + (size_t)((kk+1)*16+br)*NK + bc*4);
            q1 = *(const float4*)(Bm + (size_t)((kk+1)*16+br+8)*NK + bc*4);
        }
#pragma unroll
        for (int k=0;k<16;k++){
            const u64* ap = (const u64*)&As[cur][k][ty*4];
            u64 a0=ap[0], a1=ap[1];
            float4 c0 = *(const float4*)&Bs[cur][k][tx*8];
            float4 c1 = *(const float4*)&Bs[cur][k][tx*8+4];
            u64 bb[8];
            bb[0]=pk2(c0.x,c0.x); bb[1]=pk2(c0.y,c0.y);
            bb[2]=pk2(c0.z,c0.z); bb[3]=pk2(c0.w,c0.w);
            bb[4]=pk2(c1.x,c1.x); bb[5]=pk2(c1.y,c1.y);
            bb[6]=pk2(c1.z,c1.z); bb[7]=pk2(c1.w,c1.w);
#pragma unroll
            for (int j=0;j<8;j++){
                acc[0][j]=f2fma(a0,bb[j],acc[0][j]);
                acc[1][j]=f2fma(a1,bb[j],acc[1][j]);
            }
        }
        if (more){
            As[cur^1][aq*4+0][am]=av.x; As[cur^1][aq*4+1][am]=av.y;
            As[cur^1][aq*4+2][am]=av.z; As[cur^1][aq*4+3][am]=av.w;
            *(float4*)&Bs[cur^1][br][bc*4]   = q0;
            *(float4*)&Bs[cur^1][br+8][bc*4] = q1;
            __syncthreads();
            cur ^= 1;
        }
    }

#pragma unroll
    for (int p=0;p<2;p++){
        float4 r0a, r0b, r1a, r1b;   // rows (ty*4+2p, +1), cols tx*8..+7
        up2(acc[p][0], r0a.x, r1a.x); up2(acc[p][1], r0a.y, r1a.y);
        up2(acc[p][2], r0a.z, r1a.z); up2(acc[p][3], r0a.w, r1a.w);
        up2(acc[p][4], r0b.x, r1b.x); up2(acc[p][5], r0b.y, r1b.y);
        up2(acc[p][6], r0b.z, r1b.z); up2(acc[p][7], r0b.w, r1b.w);
        const int row0 = ty*4 + 2*p;
#pragma unroll
        for (int e=0;e<2;e++){
            float4 ga = e ? r1a : r0a;
            float4 gb = e ? r1b : r0b;
            const size_t o = (size_t)(row0+e)*NK + tx*8;
            if (mode==0){
                *(float4*)(C+o)   = ga;
                *(float4*)(C+o+4) = gb;
            } else if (mode==1){
                float4 R0 = *(const float4*)(g_AAyx + hoff + o);
                float4 R1 = *(const float4*)(g_AAyx + hoff + o + 4);
                float4 M0 = *(const float4*)(g_Mt   + hoff + o);
                float4 M1 = *(const float4*)(g_Mt   + hoff + o + 4);
                float4 X0 = *(const float4*)(A + o);        // A == X
                float4 X1 = *(const float4*)(A + o + 4);
                float4 e0, e1;
                e0.x = R0.x - ga.x - M0.x*X0.x;
                e0.y = R0.y - ga.y - M0.y*X0.y;
                e0.z = R0.z - ga.z - M0.z*X0.z;
                e0.w = R0.w - ga.w - M0.w*X0.w;
                e1.x = R1.x - gb.x - M1.x*X1.x;
                e1.y = R1.y - gb.y - M1.y*X1.y;
                e1.z = R1.z - gb.z - M1.z*X1.z;
                e1.w = R1.w - gb.w - M1.w*X1.w;
                *(float4*)(C+o)   = e0;
                *(float4*)(C+o+4) = e1;
            } else {
                float4 c0 = *(const float4*)(C+o);
                float4 c1 = *(const float4*)(C+o+4);
                c0.x+=ga.x; c0.y+=ga.y; c0.z+=ga.z; c0.w+=ga.w;
                c1.x+=gb.x; c1.y+=gb.y; c1.z+=gb.z; c1.w+=gb.w;
                *(float4*)(C+o)   = c0;
                *(float4*)(C+o+4) = c1;
            }
        }
    }
}

// ============================================================================
// Host launcher
// ============================================================================
extern "C" void kernel_launch(void* const* d_in, const int* in_sizes, int n_in,
                              void* d_out, int out_size)
{
    // Remap inputs by element count (robust to metadata ordering):
    //   32*128      -> evals (x first, then y)
    //   32*128*5000 -> pinv
    //   32*5000*256 -> feat
    const float* ev[2] = {0,0};
    const float* pv[2] = {0,0};
    const float* ft[2] = {0,0};
    int ie=0, ip=0, ifc=0;
    for (int i=0;i<n_in;i++){
        long long s = in_sizes[i];
        if      (s == (long long)NB*NK)      { if (ie <2) ev[ie++]  = (const float*)d_in[i]; }
        else if (s == (long long)NB*NK*NV)   { if (ip <2) pv[ip++]  = (const float*)d_in[i]; }
        else if (s == (long long)NB*NV*NC)   { if (ifc<2) ft[ifc++] = (const float*)d_in[i]; }
    }
    float* X = (float*)d_out;
    (void)out_size;

    dim3 gA(4, NB, 2);
    k_gemmA<<<gA, 256>>>(pv[0], ft[0], pv[1], ft[1]);

    dim3 gAA(2, NB);
    k_AA<<<gAA, 256>>>();

    k_mask<<<NB, 128>>>(ev[0], ev[1]);

    k_gj<<<NB, 256>>>();

    dim3 gS(2, NB);
    k_step<<<gS, 256>>>(X, 0);   // X0 = R * W
    k_step<<<gS, 256>>>(X, 1);   // E  = R - X*AA - M.*X
    k_step<<<gS, 256>>>(X, 2);   // X += E * W
    k_step<<<gS, 256>>>(X, 1);   // second refinement
    k_step<<<gS, 256>>>(X, 2);
}

// round 6
// speedup vs baseline: 1.3519x; 1.3519x over previous
#include <cuda_runtime.h>

#define NB 32
#define NK 128
#define NV 5000
#define NC 256
#define LMBDA 100.0f

typedef unsigned long long u64;

// ---------------- scratch (device globals; allocation is forbidden) --------
__device__ __align__(256) float g_Ax[NB*NK*NC];     // 4 MB
__device__ __align__(256) float g_Ay[NB*NK*NC];     // 4 MB
__device__ __align__(256) float g_AAxx[NB*NK*NK];   // 2 MB
__device__ __align__(256) float g_AAyx[NB*NK*NK];   // 2 MB
__device__ __align__(256) float g_W[NB*NK*NK];      // 2 MB : AA_xx^{-1}
__device__ __align__(256) float g_Mt[NB*NK*NK];     // 2 MB : LMBDA * MASK
__device__ __align__(256) float g_E[NB*NK*NK];      // 2 MB : residual

// ---------------- packed f32x2 helpers -------------------------------------
static __device__ __forceinline__ u64 pk2(float lo, float hi){
    u64 d; asm("mov.b64 %0, {%1,%2};" : "=l"(d) : "f"(lo), "f"(hi)); return d;
}
static __device__ __forceinline__ void up2(u64 v, float &lo, float &hi){
    asm("mov.b64 {%0,%1}, %2;" : "=f"(lo), "=f"(hi) : "l"(v));
}
static __device__ __forceinline__ u64 f2fma(u64 a, u64 b, u64 c){
    u64 d; asm("fma.rn.f32x2 %0, %1, %2, %3;" : "=l"(d) : "l"(a), "l"(b), "l"(c)); return d;
}
static __device__ __forceinline__ u64 f2mul(u64 a, u64 b){
    u64 d; asm("mul.rn.f32x2 %0, %1, %2;" : "=l"(d) : "l"(a), "l"(b)); return d;
}

// ============================================================================
// Kernel 1: A = pinv @ feat   per (b, which): 128x5000 @ 5000x(64-col tile)
// grid (4 n-tiles, 32 batches, 2 which), 256 threads.
// BM=128, BN=64, BK=8 double-buffered. Row-pair accumulators: each u64 acc
// holds (C[2p][j], C[2p+1][j]); A read as LDS.64 pairs, only B duplicated.
// ============================================================================
__global__ __launch_bounds__(256,2)
void k_gemmA(const float* __restrict__ Px, const float* __restrict__ Fx,
             const float* __restrict__ Py, const float* __restrict__ Fy)
{
    const int b = blockIdx.y, nt = blockIdx.x;
    const bool wy = (blockIdx.z != 0);
    const float* __restrict__ P = (wy ? Py : Px) + (size_t)b*NK*NV;
    const float* __restrict__ F = (wy ? Fy : Fx) + (size_t)b*NV*NC + nt*64;
    float* __restrict__ O = (wy ? g_Ay : g_Ax) + (size_t)b*NK*NC + nt*64;

    __shared__ __align__(16) float As[2][8][132];   // k-major: As[k][m]
    __shared__ __align__(16) float Bs[2][8][68];    // Bs[k][n]

    const int t  = threadIdx.x;
    const int tx = t & 15, ty = t >> 4;
    const int am = t >> 1, aq = t & 1;        // A loader (all 256 threads)
    const int br = t >> 4, bc = t & 15;       // B loader (t < 128)
    const bool bload = (t < 128);

    u64 acc[4][4];
#pragma unroll
    for (int p=0;p<4;p++){ acc[p][0]=0ULL; acc[p][1]=0ULL; acc[p][2]=0ULL; acc[p][3]=0ULL; }

    {   // prologue: tile 0
        float4 av = *(const float4*)(P + (size_t)am*NV + aq*4);
        As[0][aq*4+0][am]=av.x; As[0][aq*4+1][am]=av.y;
        As[0][aq*4+2][am]=av.z; As[0][aq*4+3][am]=av.w;
        if (bload){
            float4 bv = *(const float4*)(F + (size_t)br*NC + bc*4);
            *(float4*)&Bs[0][br][bc*4] = bv;
        }
    }
    __syncthreads();

    int cur = 0;
    const int NS = NV/8;   // 625, exact
#pragma unroll 1
    for (int kk=0; kk<NS; kk++){
        float4 av, bv;
        const bool more = (kk+1 < NS);
        if (more){
            av = *(const float4*)(P + (size_t)am*NV + (kk+1)*8 + aq*4);
            if (bload)
                bv = *(const float4*)(F + (size_t)((kk+1)*8+br)*NC + bc*4);
        }
#pragma unroll
        for (int k=0;k<8;k++){
            const u64* ap = (const u64*)&As[cur][k][ty*8];
            u64 a0=ap[0], a1=ap[1], a2=ap[2], a3=ap[3];
            float4 b4 = *(const float4*)&Bs[cur][k][tx*4];
            u64 b0=pk2(b4.x,b4.x), b1=pk2(b4.y,b4.y);
            u64 b2=pk2(b4.z,b4.z), b3=pk2(b4.w,b4.w);
            acc[0][0]=f2fma(a0,b0,acc[0][0]); acc[0][1]=f2fma(a0,b1,acc[0][1]);
            acc[0][2]=f2fma(a0,b2,acc[0][2]); acc[0][3]=f2fma(a0,b3,acc[0][3]);
            acc[1][0]=f2fma(a1,b0,acc[1][0]); acc[1][1]=f2fma(a1,b1,acc[1][1]);
            acc[1][2]=f2fma(a1,b2,acc[1][2]); acc[1][3]=f2fma(a1,b3,acc[1][3]);
            acc[2][0]=f2fma(a2,b0,acc[2][0]); acc[2][1]=f2fma(a2,b1,acc[2][1]);
            acc[2][2]=f2fma(a2,b2,acc[2][2]); acc[2][3]=f2fma(a2,b3,acc[2][3]);
            acc[3][0]=f2fma(a3,b0,acc[3][0]); acc[3][1]=f2fma(a3,b1,acc[3][1]);
            acc[3][2]=f2fma(a3,b2,acc[3][2]); acc[3][3]=f2fma(a3,b3,acc[3][3]);
        }
        if (more){
            As[cur^1][aq*4+0][am]=av.x; As[cur^1][aq*4+1][am]=av.y;
            As[cur^1][aq*4+2][am]=av.z; As[cur^1][aq*4+3][am]=av.w;
            if (bload) *(float4*)&Bs[cur^1][br][bc*4] = bv;
            __syncthreads();
            cur ^= 1;
        }
    }
#pragma unroll
    for (int p=0;p<4;p++){
        float4 r0, r1;
        up2(acc[p][0], r0.x, r1.x);
        up2(acc[p][1], r0.y, r1.y);
        up2(acc[p][2], r0.z, r1.z);
        up2(acc[p][3], r0.w, r1.w);
        *(float4*)(O + (size_t)(ty*8+2*p  )*NC + tx*4) = r0;
        *(float4*)(O + (size_t)(ty*8+2*p+1)*NC + tx*4) = r1;
    }
}

// ============================================================================
// Kernel 2: AA_xx = A_x A_x^T ; AA_yx = A_y A_x^T  (per b: 128x128, K=256)
// grid (2 which, 32 batches), 256 threads, 8x8 tile (4 row-pairs x 8 cols).
// ============================================================================
__global__ __launch_bounds__(256,1)
void k_AA()
{
    const int b = blockIdx.y;
    const bool yx = (blockIdx.x != 0);
    const float* __restrict__ U = (yx ? g_Ay : g_Ax) + (size_t)b*NK*NC;
    const float* __restrict__ V = g_Ax + (size_t)b*NK*NC;
    float* __restrict__ O = (yx ? g_AAyx : g_AAxx) + (size_t)b*NK*NK;

    __shared__ __align__(16) float Us[2][8][132];
    __shared__ __align__(16) float Vs[2][8][132];

    const int t = threadIdx.x, tx = t&15, ty = t>>4;
    const int um = t>>1, uq = t&1;

    u64 acc[4][8];
#pragma unroll
    for (int p=0;p<4;p++)
#pragma unroll
        for (int j=0;j<8;j++) acc[p][j]=0ULL;

    {
        float4 uv = *(const float4*)(U + (size_t)um*NC + uq*4);
        float4 vv = *(const float4*)(V + (size_t)um*NC + uq*4);
        Us[0][uq*4+0][um]=uv.x; Us[0][uq*4+1][um]=uv.y; Us[0][uq*4+2][um]=uv.z; Us[0][uq*4+3][um]=uv.w;
        Vs[0][uq*4+0][um]=vv.x; Vs[0][uq*4+1][um]=vv.y; Vs[0][uq*4+2][um]=vv.z; Vs[0][uq*4+3][um]=vv.w;
    }
    __syncthreads();

    int cur = 0;
#pragma unroll 1
    for (int kk=0; kk<NC/8; kk++){
        float4 uv, vv;
        const bool more = (kk+1 < NC/8);
        if (more){
            uv = *(const float4*)(U + (size_t)um*NC + (kk+1)*8 + uq*4);
            vv = *(const float4*)(V + (size_t)um*NC + (kk+1)*8 + uq*4);
        }
#pragma unroll
        for (int k=0;k<8;k++){
            const u64* ap = (const u64*)&Us[cur][k][ty*8];
            u64 a0=ap[0], a1=ap[1], a2=ap[2], a3=ap[3];
            float4 c0 = *(const float4*)&Vs[cur][k][tx*8];
            float4 c1 = *(const float4*)&Vs[cur][k][tx*8+4];
            u64 bb[8];
            bb[0]=pk2(c0.x,c0.x); bb[1]=pk2(c0.y,c0.y);
            bb[2]=pk2(c0.z,c0.z); bb[3]=pk2(c0.w,c0.w);
            bb[4]=pk2(c1.x,c1.x); bb[5]=pk2(c1.y,c1.y);
            bb[6]=pk2(c1.z,c1.z); bb[7]=pk2(c1.w,c1.w);
#pragma unroll
            for (int j=0;j<8;j++){
                acc[0][j]=f2fma(a0,bb[j],acc[0][j]);
                acc[1][j]=f2fma(a1,bb[j],acc[1][j]);
                acc[2][j]=f2fma(a2,bb[j],acc[2][j]);
                acc[3][j]=f2fma(a3,bb[j],acc[3][j]);
            }
        }
        if (more){
            Us[cur^1][uq*4+0][um]=uv.x; Us[cur^1][uq*4+1][um]=uv.y; Us[cur^1][uq*4+2][um]=uv.z; Us[cur^1][uq*4+3][um]=uv.w;
            Vs[cur^1][uq*4+0][um]=vv.x; Vs[cur^1][uq*4+1][um]=vv.y; Vs[cur^1][uq*4+2][um]=vv.z; Vs[cur^1][uq*4+3][um]=vv.w;
            __syncthreads();
            cur ^= 1;
        }
    }
#pragma unroll
    for (int p=0;p<4;p++){
        float4 r0a, r0b, r1a, r1b;
        up2(acc[p][0], r0a.x, r1a.x); up2(acc[p][1], r0a.y, r1a.y);
        up2(acc[p][2], r0a.z, r1a.z); up2(acc[p][3], r0a.w, r1a.w);
        up2(acc[p][4], r0b.x, r1b.x); up2(acc[p][5], r0b.y, r1b.y);
        up2(acc[p][6], r0b.z, r1b.z); up2(acc[p][7], r0b.w, r1b.w);
        *(float4*)(O + (size_t)(ty*8+2*p  )*NK + tx*8)     = r0a;
        *(float4*)(O + (size_t)(ty*8+2*p  )*NK + tx*8 + 4) = r0b;
        *(float4*)(O + (size_t)(ty*8+2*p+1)*NK + tx*8)     = r1a;
        *(float4*)(O + (size_t)(ty*8+2*p+1)*NK + tx*8 + 4) = r1b;
    }
}

// ============================================================================
// Kernel 3: Mt[b,i,k] = LMBDA * MASK[b,i,k]
//   rows i <- evals_y terms, cols k <- evals_x terms (matches reference).
// ============================================================================
__global__ void k_mask(const float* __restrict__ evx, const float* __restrict__ evy)
{
    __shared__ float f1[NK], h1[NK], f2[NK], h2[NK], red[NK];
    const int b = blockIdx.x, t = threadIdx.x;
    float ex = evx[b*NK+t], ey = evy[b*NK+t];
    red[t] = fmaxf(ex, ey);
    __syncthreads();
    for (int s=64; s>0; s>>=1){
        if (t<s) red[t] = fmaxf(red[t], red[t+s]);
        __syncthreads();
    }
    const float scale = red[0];
    float e1 = sqrtf(ex/scale);
    float e2 = sqrtf(ey/scale);
    float d1 = 1.0f/(e1*e1+1.0f);
    float d2 = 1.0f/(e2*e2+1.0f);
    f1[t] = e1*d1; h1[t] = d1;
    f2[t] = e2*d2; h2[t] = d2;
    __syncthreads();
    const float mf1 = f1[t], mh1 = h1[t];
    float* out = g_Mt + (size_t)b*NK*NK;
#pragma unroll 4
    for (int i=0;i<NK;i++){
        float dre = f2[i]-mf1, dim = h2[i]-mh1;
        out[(size_t)i*NK + t] = LMBDA*(dre*dre + dim*dim);
    }
}

// ============================================================================
// Kernel 4: register-resident Gauss-Jordan inverse: g_W[b] = inv(AA_xx[b])
// One block per b, 256 threads. Thread (rb,cb) owns an 8x8 block as u64[8][4]
// (packed f32x2 column pairs).
// CRITICAL: pivot sub-index jr is a fully-unrolled compile-time constant so
// every index into M[][] is static -> no local-memory spill (the round-5
// profile showed the dynamic-index version spilling: 262us, fma=1.2%).
// Per pivot: publish factor column + scaled pivot row via double-buffered
// shared; 2 barriers per step. SPD, no pivoting.
// ============================================================================
__global__ __launch_bounds__(256,1)
void k_gj()
{
    const int b = blockIdx.x, t = threadIdx.x;
    const int rb = t >> 4, cb = t & 15;     // 16x16 grid of 8x8 blocks
    const float* __restrict__ A = g_AAxx + (size_t)b*NK*NK;
    float* __restrict__ W = g_W + (size_t)b*NK*NK;

    __shared__ __align__(16) float prow[2][NK];
    __shared__ __align__(16) float fcol[2][NK];

    u64 M[8][4];
#pragma unroll
    for (int r=0;r<8;r++){
        const u64* src = (const u64*)(A + (size_t)(rb*8+r)*NK + cb*8);
        M[r][0]=src[0]; M[r][1]=src[1]; M[r][2]=src[2]; M[r][3]=src[3];
    }

#pragma unroll 1
    for (int jb=0; jb<16; jb++){
        const bool colown = (cb == jb);
        const bool rowown = (rb == jb);
#pragma unroll
        for (int jr=0; jr<8; jr++){          // jr is compile-time constant
            const int j  = jb*8 + jr;
            const int pb = j & 1;
            const int jc = jr >> 1;          // static
            if (colown){
#pragma unroll
                for (int r=0;r<8;r++){
                    float lo,hi; up2(M[r][jc], lo, hi);
                    fcol[pb][rb*8+r] = (jr&1) ? hi : lo;
                }
            }
            __syncthreads();
            const float d   = fcol[pb][j];
            const float inv = __frcp_rn(d);
            if (rowown){
                const u64 iv2 = pk2(inv,inv);
#pragma unroll
                for (int c=0;c<4;c++) M[jr][c] = f2mul(M[jr][c], iv2);
                if (colown){
                    float lo,hi; up2(M[jr][jc], lo, hi);
                    if (jr&1) hi = inv; else lo = inv;
                    M[jr][jc] = pk2(lo,hi);
                }
#pragma unroll
                for (int c=0;c<4;c++)
                    *(u64*)&prow[pb][cb*8 + c*2] = M[jr][c];
            }
            __syncthreads();
            u64 p2[4];
#pragma unroll
            for (int c=0;c<4;c++) p2[c] = *(const u64*)&prow[pb][cb*8 + c*2];
#pragma unroll
            for (int r=0;r<8;r++){
                const float fr  = fcol[pb][rb*8+r];
                const bool piv  = rowown && (r==jr);
                const float frz = piv ? 0.0f : fr;
                const u64 nf2 = pk2(-frz, -frz);
                M[r][0] = f2fma(nf2, p2[0], M[r][0]);
                M[r][1] = f2fma(nf2, p2[1], M[r][1]);
                M[r][2] = f2fma(nf2, p2[2], M[r][2]);
                M[r][3] = f2fma(nf2, p2[3], M[r][3]);
                if (colown && !piv){
                    float lo,hi; up2(M[r][jc], lo, hi);
                    float v = -fr*inv;
                    if (jr&1) hi = v; else lo = v;
                    M[r][jc] = pk2(lo,hi);
                }
            }
        }
    }
#pragma unroll
    for (int r=0;r<8;r++){
        u64* dst = (u64*)(W + (size_t)(rb*8+r)*NK + cb*8);
        dst[0]=M[r][0]; dst[1]=M[r][1]; dst[2]=M[r][2]; dst[3]=M[r][3];
    }
}

// ============================================================================
// Kernel 5: solve steps (per b, 64-row halves; 4 rows x 8 cols per thread)
//   mode 0: X = R * W            (R = AA_yx)
//   mode 1: E = R - X*AA_xx - Mt .* X
//   mode 2: X += E * W
// ============================================================================
__global__ __launch_bounds__(256,2)
void k_step(float* __restrict__ X, int mode)
{
    const int b = blockIdx.y, half = blockIdx.x;
    const size_t boff = (size_t)b*NK*NK;
    const size_t hoff = boff + (size_t)half*64*NK;

    const float* A; const float* Bm; float* C;
    if (mode==0)      { A = g_AAyx + hoff; Bm = g_W    + boff; C = X   + hoff; }
    else if (mode==1) { A = X      + hoff; Bm = g_AAxx + boff; C = g_E + hoff; }
    else              { A = g_E    + hoff; Bm = g_W    + boff; C = X   + hoff; }

    __shared__ __align__(16) float As[2][16][68];    // As[k][m], m<64
    __shared__ __align__(16) float Bs[2][16][132];   // Bs[k][n]

    const int t = threadIdx.x;
    const int tx = t&15, ty = t>>4;
    const int am = t>>2, aq = t&3;
    const int br = t>>5, bc = t&31;

    u64 acc[2][8];
#pragma unroll
    for (int p=0;p<2;p++)
#pragma unroll
        for (int j=0;j<8;j++) acc[p][j]=0ULL;

    {
        float4 av = *(const float4*)(A + (size_t)am*NK + aq*4);
        As[0][aq*4+0][am]=av.x; As[0][aq*4+1][am]=av.y;
        As[0][aq*4+2][am]=av.z; As[0][aq*4+3][am]=av.w;
        float4 b0 = *(const float4*)(Bm + (size_t)br*NK + bc*4);
        float4 b1 = *(const float4*)(Bm + (size_t)(br+8)*NK + bc*4);
        *(float4*)&Bs[0][br][bc*4]   = b0;
        *(float4*)&Bs[0][br+8][bc*4] = b1;
    }
    __syncthreads();

    int cur = 0;
#pragma unroll 1
    for (int kk=0; kk<8; kk++){
        float4 av, q0, q1;
        const bool more = (kk < 7);
        if (more){
            av = *(const float4*)(A + (size_t)am*NK + (kk+1)*16 + aq*4);
            q0 = *(const float4*)(Bm + (size_t)((kk+1)*16+br)*NK + bc*4);
            q1 = *(const float4*)(Bm + (size_t)((kk+1)*16+br+8)*NK + bc*4);
        }
#pragma unroll
        for (int k=0;k<16;k++){
            const u64* ap = (const u64*)&As[cur][k][ty*4];
            u64 a0=ap[0], a1=ap[1];
            float4 c0 = *(const float4*)&Bs[cur][k][tx*8];
            float4 c1 = *(const float4*)&Bs[cur][k][tx*8+4];
            u64 bb[8];
            bb[0]=pk2(c0.x,c0.x); bb[1]=pk2(c0.y,c0.y);
            bb[2]=pk2(c0.z,c0.z); bb[3]=pk2(c0.w,c0.w);
            bb[4]=pk2(c1.x,c1.x); bb[5]=pk2(c1.y,c1.y);
            bb[6]=pk2(c1.z,c1.z); bb[7]=pk2(c1.w,c1.w);
#pragma unroll
            for (int j=0;j<8;j++){
                acc[0][j]=f2fma(a0,bb[j],acc[0][j]);
                acc[1][j]=f2fma(a1,bb[j],acc[1][j]);
            }
        }
        if (more){
            As[cur^1][aq*4+0][am]=av.x; As[cur^1][aq*4+1][am]=av.y;
            As[cur^1][aq*4+2][am]=av.z; As[cur^1][aq*4+3][am]=av.w;
            *(float4*)&Bs[cur^1][br][bc*4]   = q0;
            *(float4*)&Bs[cur^1][br+8][bc*4] = q1;
            __syncthreads();
            cur ^= 1;
        }
    }

#pragma unroll
    for (int p=0;p<2;p++){
        float4 r0a, r0b, r1a, r1b;   // rows (ty*4+2p, +1), cols tx*8..+7
        up2(acc[p][0], r0a.x, r1a.x); up2(acc[p][1], r0a.y, r1a.y);
        up2(acc[p][2], r0a.z, r1a.z); up2(acc[p][3], r0a.w, r1a.w);
        up2(acc[p][4], r0b.x, r1b.x); up2(acc[p][5], r0b.y, r1b.y);
        up2(acc[p][6], r0b.z, r1b.z); up2(acc[p][7], r0b.w, r1b.w);
        const int row0 = ty*4 + 2*p;
#pragma unroll
        for (int e=0;e<2;e++){
            float4 ga = e ? r1a : r0a;
            float4 gb = e ? r1b : r0b;
            const size_t o = (size_t)(row0+e)*NK + tx*8;
            if (mode==0){
                *(float4*)(C+o)   = ga;
                *(float4*)(C+o+4) = gb;
            } else if (mode==1){
                float4 R0 = *(const float4*)(g_AAyx + hoff + o);
                float4 R1 = *(const float4*)(g_AAyx + hoff + o + 4);
                float4 M0 = *(const float4*)(g_Mt   + hoff + o);
                float4 M1 = *(const float4*)(g_Mt   + hoff + o + 4);
                float4 X0 = *(const float4*)(A + o);        // A == X
                float4 X1 = *(const float4*)(A + o + 4);
                float4 e0, e1;
                e0.x = R0.x - ga.x - M0.x*X0.x;
                e0.y = R0.y - ga.y - M0.y*X0.y;
                e0.z = R0.z - ga.z - M0.z*X0.z;
                e0.w = R0.w - ga.w - M0.w*X0.w;
                e1.x = R1.x - gb.x - M1.x*X1.x;
                e1.y = R1.y - gb.y - M1.y*X1.y;
                e1.z = R1.z - gb.z - M1.z*X1.z;
                e1.w = R1.w - gb.w - M1.w*X1.w;
                *(float4*)(C+o)   = e0;
                *(float4*)(C+o+4) = e1;
            } else {
                float4 c0 = *(const float4*)(C+o);
                float4 c1 = *(const float4*)(C+o+4);
                c0.x+=ga.x; c0.y+=ga.y; c0.z+=ga.z; c0.w+=ga.w;
                c1.x+=gb.x; c1.y+=gb.y; c1.z+=gb.z; c1.w+=gb.w;
                *(float4*)(C+o)   = c0;
                *(float4*)(C+o+4) = c1;
            }
        }
    }
}

// ============================================================================
// Host launcher
// ============================================================================
extern "C" void kernel_launch(void* const* d_in, const int* in_sizes, int n_in,
                              void* d_out, int out_size)
{
    // Remap inputs by element count (robust to metadata ordering):
    //   32*128      -> evals (x first, then y)
    //   32*128*5000 -> pinv
    //   32*5000*256 -> feat
    const float* ev[2] = {0,0};
    const float* pv[2] = {0,0};
    const float* ft[2] = {0,0};
    int ie=0, ip=0, ifc=0;
    for (int i=0;i<n_in;i++){
        long long s = in_sizes[i];
        if      (s == (long long)NB*NK)      { if (ie <2) ev[ie++]  = (const float*)d_in[i]; }
        else if (s == (long long)NB*NK*NV)   { if (ip <2) pv[ip++]  = (const float*)d_in[i]; }
        else if (s == (long long)NB*NV*NC)   { if (ifc<2) ft[ifc++] = (const float*)d_in[i]; }
    }
    float* X = (float*)d_out;
    (void)out_size;

    dim3 gA(4, NB, 2);
    k_gemmA<<<gA, 256>>>(pv[0], ft[0], pv[1], ft[1]);

    dim3 gAA(2, NB);
    k_AA<<<gAA, 256>>>();

    k_mask<<<NB, 128>>>(ev[0], ev[1]);

    k_gj<<<NB, 256>>>();

    dim3 gS(2, NB);
    k_step<<<gS, 256>>>(X, 0);   // X0 = R * W
    k_step<<<gS, 256>>>(X, 1);   // E  = R - X*AA - M.*X
    k_step<<<gS, 256>>>(X, 2);   // X += E * W
    k_step<<<gS, 256>>>(X, 1);   // second refinement
    k_step<<<gS, 256>>>(X, 2);
}